// round 1
// baseline (speedup 1.0000x reference)
#include <cuda_runtime.h>

#define LOG2E 1.4426950408889634f

// ---------------- scratch (no allocations allowed) ----------------
__device__ float g_conv3[49152];
__device__ float g_conv1[49152];
__device__ float g_v[49152];
__device__ float g_q[49152];
__device__ float g_scale[16];     // [0:4) scale3 [4:8) shift3 [8:12) scale1 [12:16) shift1
__device__ int   g_m[12];
__device__ float g_qmax[12];
__device__ float g_s0n[12];       // (sum of v over zero-q positions)/4096
__device__ float g_A[12][4096];   // nonzero q values
__device__ float g_B[12][4096];   // (q - qmax) * LOG2E
__device__ float g_Vnz[12][4096]; // v at nonzero-q positions
__device__ int   g_idx[12][4096]; // original position within slice
__device__ float g_w[12][4096];   // v / Z
__device__ float g_patt[49152];   // written only at nonzero-q positions
__device__ float g_pattz[12];     // shared Patt value for all zero-q positions

__device__ __forceinline__ float ex2(float x) {
    float y; asm("ex2.approx.ftz.f32 %0, %1;" : "=f"(y) : "f"(x)); return y;
}

// ---------------- conv3x3x3 (pad 1) + conv1x1x1 fused ----------------
__global__ void conv_kernel(const float* __restrict__ x, const float* __restrict__ W3,
                            const float* __restrict__ b3, const float* __restrict__ W1,
                            const float* __restrict__ b1) {
    int idx = blockIdx.x * blockDim.x + threadIdx.x;
    if (idx >= 49152) return;
    int c = idx / 12288;
    int r = idx - c * 12288;
    int d = r >> 12;
    int p = r & 4095;
    int h = p >> 6;
    int w = p & 63;

    float acc = b3[c];
    #pragma unroll
    for (int ci = 0; ci < 4; ci++) {
        const float* wp = W3 + (c * 4 + ci) * 27;
        const float* xp = x + ci * 12288;
        #pragma unroll
        for (int kd = 0; kd < 3; kd++) {
            int zd = d + kd - 1;
            if ((unsigned)zd >= 3u) continue;
            #pragma unroll
            for (int kh = 0; kh < 3; kh++) {
                int zh = h + kh - 1;
                if ((unsigned)zh >= 64u) continue;
                #pragma unroll
                for (int kw = 0; kw < 3; kw++) {
                    int zw = w + kw - 1;
                    if ((unsigned)zw >= 64u) continue;
                    acc += wp[kd * 9 + kh * 3 + kw] * xp[zd * 4096 + zh * 64 + zw];
                }
            }
        }
    }
    g_conv3[idx] = acc;

    float acc1 = b1[c];
    #pragma unroll
    for (int ci = 0; ci < 4; ci++)
        acc1 += W1[c * 4 + ci] * x[ci * 12288 + d * 4096 + p];
    g_conv1[idx] = acc1;
}

// ---------------- BatchNorm batch stats (training mode, biased var) ----------------
__global__ void stats_kernel(const float* __restrict__ g3, const float* __restrict__ be3,
                             const float* __restrict__ g1, const float* __restrict__ be1) {
    int ch = blockIdx.x;  // 0..3 -> conv3 channels, 4..7 -> conv1 channels
    const float* src = (ch < 4) ? g_conv3 : g_conv1;
    int c = ch & 3;
    const float* pp = src + c * 12288;
    float s = 0.f, sq = 0.f;
    for (int i = threadIdx.x; i < 12288; i += 256) {
        float v = pp[i]; s += v; sq += v * v;
    }
    __shared__ float sh1[256], sh2[256];
    sh1[threadIdx.x] = s; sh2[threadIdx.x] = sq;
    __syncthreads();
    for (int o = 128; o > 0; o >>= 1) {
        if (threadIdx.x < o) { sh1[threadIdx.x] += sh1[threadIdx.x + o]; sh2[threadIdx.x] += sh2[threadIdx.x + o]; }
        __syncthreads();
    }
    if (threadIdx.x == 0) {
        float mean = sh1[0] * (1.f / 12288.f);
        float var  = sh2[0] * (1.f / 12288.f) - mean * mean;
        float rstd = rsqrtf(var + 1e-5f);
        float gamma = (ch < 4) ? g3[c] : g1[c];
        float beta  = (ch < 4) ? be3[c] : be1[c];
        float sc = gamma * rstd;
        int o = (ch < 4) ? 0 : 8;
        g_scale[o + c]     = sc;
        g_scale[o + 4 + c] = beta - mean * sc;
    }
}

// ---------------- apply bn + relu ----------------
__global__ void bnrelu_kernel() {
    int idx = blockIdx.x * blockDim.x + threadIdx.x;
    if (idx >= 49152) return;
    int c = idx / 12288;
    g_v[idx] = fmaxf(fmaf(g_conv3[idx], g_scale[c],     g_scale[4 + c]),  0.f);
    g_q[idx] = fmaxf(fmaf(g_conv1[idx], g_scale[8 + c], g_scale[12 + c]), 0.f);
}

// ---------------- per-slice: qmax, deterministic nonzero compaction, zero-v sum ----------------
__global__ void prep_kernel() {
    int sl = blockIdx.x;             // c*3 + d
    int base = sl * 4096;
    int t = threadIdx.x;             // 512 threads
    __shared__ float shf[512];
    __shared__ int   shi[512];

    // qmax over slice
    float mx = 0.f;
    for (int i = t; i < 4096; i += 512) mx = fmaxf(mx, g_q[base + i]);
    shf[t] = mx; __syncthreads();
    for (int o = 256; o > 0; o >>= 1) {
        if (t < o) shf[t] = fmaxf(shf[t], shf[t + o]);
        __syncthreads();
    }
    float qmax = shf[0];
    __syncthreads();

    // each thread owns 8 contiguous elements; count nonzeros
    int b0 = t * 8;
    int cnt = 0;
    #pragma unroll
    for (int k = 0; k < 8; k++) cnt += (g_q[base + b0 + k] > 0.f);
    shi[t] = cnt; __syncthreads();
    // inclusive Hillis-Steele scan over 512 counts
    for (int o = 1; o < 512; o <<= 1) {
        int add = (t >= o) ? shi[t - o] : 0;
        __syncthreads();
        shi[t] += add;
        __syncthreads();
    }
    int off = shi[t] - cnt;
    int m = shi[511];

    // ordered compaction + zero-position v sum
    float s0 = 0.f;
    #pragma unroll
    for (int k = 0; k < 8; k++) {
        int j = b0 + k;
        float qv = g_q[base + j];
        if (qv > 0.f) {
            g_A[sl][off]   = qv;
            g_B[sl][off]   = (qv - qmax) * LOG2E;
            g_Vnz[sl][off] = g_v[base + j];
            g_idx[sl][off] = j;
            off++;
        } else {
            s0 += g_v[base + j];
        }
    }
    __syncthreads();
    shf[t] = s0; __syncthreads();
    for (int o = 256; o > 0; o >>= 1) {
        if (t < o) shf[t] += shf[t + o];
        __syncthreads();
    }
    if (t == 0) {
        g_m[sl] = m;
        g_qmax[sl] = qmax;
        g_s0n[sl] = shf[0] * (1.f / 4096.f);
    }
}

// ---------------- pass A: Z_i for nonzero rows, w_i = v_i / Z_i ----------------
__global__ void zpass_kernel() {
    int sl = blockIdx.x;
    int m = g_m[sl];
    if ((int)(blockIdx.y * 256) >= m) return;    // whole-block uniform exit
    __shared__ float shB[4096];
    for (int i = threadIdx.x; i < m; i += 256) shB[i] = g_B[sl][i];
    __syncthreads();
    int row = blockIdx.y * 256 + threadIdx.x;
    if (row >= m) return;
    float qi = g_A[sl][row];
    float a0 = 0.f, a1 = 0.f, a2 = 0.f, a3 = 0.f;
    int s = 0, m4 = m & ~3;
    for (; s < m4; s += 4) {
        a0 += ex2(qi * shB[s]);
        a1 += ex2(qi * shB[s + 1]);
        a2 += ex2(qi * shB[s + 2]);
        a3 += ex2(qi * shB[s + 3]);
    }
    for (; s < m; s++) a0 += ex2(qi * shB[s]);
    float Bzero = -g_qmax[sl] * LOG2E;
    float Z = (a0 + a1) + (a2 + a3) + (float)(4096 - m) * ex2(qi * Bzero);
    g_w[sl][row] = g_Vnz[sl][row] / Z;
}

// ---------------- pass B: Patt_j for nonzero columns (+ shared zero-column value) ----------------
__global__ void patt_kernel() {
    int sl = blockIdx.x;
    int m = g_m[sl];
    if ((int)(blockIdx.y * 256) > m) return;     // rows 0..m inclusive (row m = zero-column)
    __shared__ float shA[4096];
    __shared__ float shW[4096];
    for (int i = threadIdx.x; i < m; i += 256) { shA[i] = g_A[sl][i]; shW[i] = g_w[sl][i]; }
    __syncthreads();
    int row = blockIdx.y * 256 + threadIdx.x;
    if (row > m) return;
    float Bj = (row < m) ? g_B[sl][row] : (-g_qmax[sl] * LOG2E);
    float a0 = 0.f, a1 = 0.f, a2 = 0.f, a3 = 0.f;
    int s = 0, m4 = m & ~3;
    for (; s < m4; s += 4) {
        a0 = fmaf(shW[s],     ex2(Bj * shA[s]),     a0);
        a1 = fmaf(shW[s + 1], ex2(Bj * shA[s + 1]), a1);
        a2 = fmaf(shW[s + 2], ex2(Bj * shA[s + 2]), a2);
        a3 = fmaf(shW[s + 3], ex2(Bj * shA[s + 3]), a3);
    }
    for (; s < m; s++) a0 = fmaf(shW[s], ex2(Bj * shA[s]), a0);
    float res = (a0 + a1) + (a2 + a3) + g_s0n[sl];
    if (row < m) g_patt[sl * 4096 + g_idx[sl][row]] = res;
    else         g_pattz[sl] = res;
}

// ---------------- depth attention (D=3) + epilogue ----------------
__global__ void final_kernel(const float* __restrict__ x, const float* __restrict__ gama,
                             float* __restrict__ out) {
    int idx = blockIdx.x * blockDim.x + threadIdx.x;   // c*4096 + p, 16384 total
    if (idx >= 16384) return;
    int c = idx >> 12;
    int p = idx & 4095;
    int base = c * 12288 + p;

    float qv[3], vv[3];
    #pragma unroll
    for (int d = 0; d < 3; d++) { qv[d] = g_q[base + d * 4096]; vv[d] = g_v[base + d * 4096]; }
    float qm = fmaxf(qv[0], fmaxf(qv[1], qv[2]));

    float datt0 = 0.f, datt1 = 0.f, datt2 = 0.f;
    #pragma unroll
    for (int i = 0; i < 3; i++) {
        float e0 = ex2(qv[i] * (qv[0] - qm) * LOG2E);
        float e1 = ex2(qv[i] * (qv[1] - qm) * LOG2E);
        float e2 = ex2(qv[i] * (qv[2] - qm) * LOG2E);
        float rz = vv[i] / (e0 + e1 + e2);
        datt0 = fmaf(rz, e0, datt0);
        datt1 = fmaf(rz, e1, datt1);
        datt2 = fmaf(rz, e2, datt2);
    }
    float datt[3] = {datt0, datt1, datt2};
    float g = gama[0];
    #pragma unroll
    for (int d = 0; d < 3; d++) {
        int gi = base + d * 4096;            // == (c*3+d)*4096 + p
        int sl = c * 3 + d;
        float patt = (qv[d] > 0.f) ? g_patt[gi] : g_pattz[sl];
        out[gi] = fmaf(g, patt + datt[d], x[gi]);
    }
}

// ---------------- launch ----------------
extern "C" void kernel_launch(void* const* d_in, const int* in_sizes, int n_in,
                              void* d_out, int out_size) {
    const float* x    = (const float*)d_in[0];
    const float* W3   = (const float*)d_in[1];
    const float* b3   = (const float*)d_in[2];
    const float* g3   = (const float*)d_in[3];
    const float* be3  = (const float*)d_in[4];
    const float* W1   = (const float*)d_in[5];
    const float* b1   = (const float*)d_in[6];
    const float* g1   = (const float*)d_in[7];
    const float* be1  = (const float*)d_in[8];
    const float* gama = (const float*)d_in[9];
    float* out = (float*)d_out;

    conv_kernel<<<192, 256>>>(x, W3, b3, W1, b1);
    stats_kernel<<<8, 256>>>(g3, be3, g1, be1);
    bnrelu_kernel<<<192, 256>>>();
    prep_kernel<<<12, 512>>>();
    zpass_kernel<<<dim3(12, 16), 256>>>();
    patt_kernel<<<dim3(12, 17), 256>>>();
    final_kernel<<<64, 256>>>(x, gama, out);
}

// round 2
// speedup vs baseline: 1.2863x; 1.2863x over previous
#include <cuda_runtime.h>

#define LOG2E 1.4426950408889634f
#define KG 512           // interpolation grid size
#define JS 8             // j-split for grid kernels

// ---------------- scratch ----------------
__device__ float g_conv3[49152];
__device__ float g_conv1[49152];
__device__ float g_v[49152];
__device__ float g_q[49152];
__device__ float g_scale[16];     // [0:4) scale3 [4:8) shift3 [8:12) scale1 [12:16) shift1
__device__ int   g_m[12];
__device__ float g_qmax[12];
__device__ float g_s0n[12];
__device__ float g_A[12][4096];   // compacted nonzero q
__device__ float g_Vnz[12][4096]; // v at those positions
__device__ float g_U[12][4096];   // u_i coefficients for G
__device__ float g_Fp[12][JS][KG];
__device__ float g_Gp[12][JS][KG];
__device__ float g_patt[49152];

__device__ __forceinline__ float ex2(float x) {
    float y; asm("ex2.approx.ftz.f32 %0, %1;" : "=f"(y) : "f"(x)); return y;
}

// ---------------- conv3x3x3 (pad 1) + conv1x1x1 fused ----------------
__global__ void conv_kernel(const float* __restrict__ x, const float* __restrict__ W3,
                            const float* __restrict__ b3, const float* __restrict__ W1,
                            const float* __restrict__ b1) {
    int idx = blockIdx.x * blockDim.x + threadIdx.x;
    if (idx >= 49152) return;
    int c = idx / 12288;
    int r = idx - c * 12288;
    int d = r >> 12;
    int p = r & 4095;
    int h = p >> 6;
    int w = p & 63;

    float acc = b3[c];
    #pragma unroll
    for (int ci = 0; ci < 4; ci++) {
        const float* wp = W3 + (c * 4 + ci) * 27;
        const float* xp = x + ci * 12288;
        #pragma unroll
        for (int kd = 0; kd < 3; kd++) {
            int zd = d + kd - 1;
            if ((unsigned)zd >= 3u) continue;
            #pragma unroll
            for (int kh = 0; kh < 3; kh++) {
                int zh = h + kh - 1;
                if ((unsigned)zh >= 64u) continue;
                #pragma unroll
                for (int kw = 0; kw < 3; kw++) {
                    int zw = w + kw - 1;
                    if ((unsigned)zw >= 64u) continue;
                    acc += wp[kd * 9 + kh * 3 + kw] * xp[zd * 4096 + zh * 64 + zw];
                }
            }
        }
    }
    g_conv3[idx] = acc;

    float acc1 = b1[c];
    #pragma unroll
    for (int ci = 0; ci < 4; ci++)
        acc1 += W1[c * 4 + ci] * x[ci * 12288 + d * 4096 + p];
    g_conv1[idx] = acc1;
}

// ---------------- BatchNorm batch stats ----------------
__global__ void stats_kernel(const float* __restrict__ g3, const float* __restrict__ be3,
                             const float* __restrict__ g1, const float* __restrict__ be1) {
    int ch = blockIdx.x;  // 0..3 conv3, 4..7 conv1
    const float* src = (ch < 4) ? g_conv3 : g_conv1;
    int c = ch & 3;
    const float4* pp = (const float4*)(src + c * 12288);
    float s = 0.f, sq = 0.f;
    for (int i = threadIdx.x; i < 3072; i += 256) {
        float4 v = pp[i];
        s += (v.x + v.y) + (v.z + v.w);
        sq += (v.x * v.x + v.y * v.y) + (v.z * v.z + v.w * v.w);
    }
    // warp + block reduce
    for (int o = 16; o > 0; o >>= 1) {
        s  += __shfl_xor_sync(0xffffffffu, s, o);
        sq += __shfl_xor_sync(0xffffffffu, sq, o);
    }
    __shared__ float sh1[8], sh2[8];
    int wid = threadIdx.x >> 5, lane = threadIdx.x & 31;
    if (lane == 0) { sh1[wid] = s; sh2[wid] = sq; }
    __syncthreads();
    if (threadIdx.x == 0) {
        float S = 0.f, SQ = 0.f;
        #pragma unroll
        for (int i = 0; i < 8; i++) { S += sh1[i]; SQ += sh2[i]; }
        float mean = S * (1.f / 12288.f);
        float var  = SQ * (1.f / 12288.f) - mean * mean;
        float rstd = rsqrtf(var + 1e-5f);
        float gamma = (ch < 4) ? g3[c] : g1[c];
        float beta  = (ch < 4) ? be3[c] : be1[c];
        float sc = gamma * rstd;
        int o = (ch < 4) ? 0 : 8;
        g_scale[o + c]     = sc;
        g_scale[o + 4 + c] = beta - mean * sc;
    }
}

// ---------------- bn+relu, per-slice qmax / compaction / zero-v sum ----------------
__global__ void prep_kernel() {
    int sl = blockIdx.x;
    int base = sl * 4096;
    int t = threadIdx.x;                 // 512
    int c = sl / 3;
    int lane = t & 31, wid = t >> 5;
    __shared__ float shf[16];
    __shared__ float shs[16];
    __shared__ int   shw[16];

    float sc3 = g_scale[c],     sh3 = g_scale[4 + c];
    float sc1 = g_scale[8 + c], sh1 = g_scale[12 + c];

    float qv[8], vv[8];
    int b0 = base + t * 8;
    #pragma unroll
    for (int k = 0; k < 8; k++) {
        int j = b0 + k;
        qv[k] = fmaxf(fmaf(g_conv1[j], sc1, sh1), 0.f);
        vv[k] = fmaxf(fmaf(g_conv3[j], sc3, sh3), 0.f);
        g_q[j] = qv[k];
        g_v[j] = vv[k];
    }

    // qmax, zero-v sum, nonzero count (local)
    float mx = 0.f, s0 = 0.f;
    int cnt = 0;
    #pragma unroll
    for (int k = 0; k < 8; k++) {
        mx = fmaxf(mx, qv[k]);
        if (qv[k] > 0.f) cnt++; else s0 += vv[k];
    }
    // warp reductions
    float m2 = mx, z2 = s0;
    for (int o = 16; o > 0; o >>= 1) {
        m2 = fmaxf(m2, __shfl_xor_sync(0xffffffffu, m2, o));
        z2 += __shfl_xor_sync(0xffffffffu, z2, o);
    }
    // warp inclusive scan of cnt
    int inc = cnt;
    #pragma unroll
    for (int o = 1; o < 32; o <<= 1) {
        int n = __shfl_up_sync(0xffffffffu, inc, o);
        if (lane >= o) inc += n;
    }
    if (lane == 31) shw[wid] = inc;
    if (lane == 0) { shf[wid] = m2; shs[wid] = z2; }
    __syncthreads();
    if (wid == 0) {
        int sv = (lane < 16) ? shw[lane] : 0;
        #pragma unroll
        for (int o = 1; o < 16; o <<= 1) {
            int n = __shfl_up_sync(0xffffffffu, sv, o);
            if (lane >= o) sv += n;
        }
        if (lane < 16) shw[lane] = sv;
        float fm = (lane < 16) ? shf[lane] : 0.f;
        float fz = (lane < 16) ? shs[lane] : 0.f;
        for (int o = 8; o > 0; o >>= 1) {
            fm = fmaxf(fm, __shfl_xor_sync(0xffffffffu, fm, o));
            fz += __shfl_xor_sync(0xffffffffu, fz, o);
        }
        if (lane == 0) { shf[0] = fm; shs[0] = fz; }
    }
    __syncthreads();

    int off = (wid ? shw[wid - 1] : 0) + inc - cnt;
    #pragma unroll
    for (int k = 0; k < 8; k++) {
        if (qv[k] > 0.f) {
            g_A[sl][off]   = qv[k];
            g_Vnz[sl][off] = vv[k];
            off++;
        }
    }
    if (t == 0) {
        g_m[sl]    = shw[15];
        g_qmax[sl] = shf[0];
        g_s0n[sl]  = shs[0] * (1.f / 4096.f);
    }
}

// ---------------- grid tabulation of F(t) = sum_j exp(t*(q_j - qmax)) ----------------
__global__ void gridF_kernel() {
    int sl = blockIdx.x;
    int m = g_m[sl];
    int k = blockIdx.y * 128 + threadIdx.x;
    float qmax = g_qmax[sl];
    float t = (float)k * (qmax * (1.f / (KG - 1)));
    float tl = t * LOG2E;
    float cn = -qmax * tl;                 // arg = A[j]*tl + cn
    int chunk = (m + JS - 1) / JS;
    int j0 = blockIdx.z * chunk;
    int j1 = min(j0 + chunk, m);
    const float* __restrict__ A = g_A[sl];
    float a0 = 0.f, a1 = 0.f, a2 = 0.f, a3 = 0.f;
    int j = j0;
    for (; j + 4 <= j1; j += 4) {
        a0 += ex2(fmaf(A[j],     tl, cn));
        a1 += ex2(fmaf(A[j + 1], tl, cn));
        a2 += ex2(fmaf(A[j + 2], tl, cn));
        a3 += ex2(fmaf(A[j + 3], tl, cn));
    }
    for (; j < j1; j++) a0 += ex2(fmaf(A[j], tl, cn));
    g_Fp[sl][blockIdx.z][k] = (a0 + a1) + (a2 + a3);
}

// ---------------- reduce F, compute w_i and u_i per nonzero row ----------------
__global__ void wpass_kernel() {
    int sl = blockIdx.x;
    int m = g_m[sl];
    int t = threadIdx.x;                  // 512
    float qmax = g_qmax[sl];
    __shared__ float shF[KG];
    float f = 0.f;
    #pragma unroll
    for (int j = 0; j < JS; j++) f += g_Fp[sl][j][t];
    float tk = (float)t * (qmax * (1.f / (KG - 1)));
    f += (float)(4096 - m) * ex2(-tk * qmax * LOG2E);
    shF[t] = f;
    __syncthreads();

    float inv = (qmax > 0.f) ? (float)(KG - 1) / qmax : 0.f;
    int rpb = (m + 3) / 4;
    int r0 = blockIdx.y * rpb;
    int r1 = min(r0 + rpb, m);
    for (int r = r0 + t; r < r1; r += 512) {
        float q = g_A[sl][r];
        float u = q * inv;
        int k0 = min((int)u, KG - 2);
        float fr = u - (float)k0;
        float F = fmaf(shF[k0 + 1] - shF[k0], fr, shF[k0]);
        float w = g_Vnz[sl][r] / F;
        g_U[sl][r] = w * ex2(-q * qmax * LOG2E);
    }
}

// ---------------- grid tabulation of G(t) = sum_i u_i exp(t*q_i) ----------------
__global__ void gridG_kernel() {
    int sl = blockIdx.x;
    int m = g_m[sl];
    int k = blockIdx.y * 128 + threadIdx.x;
    float qmax = g_qmax[sl];
    float tl = (float)k * (qmax * (1.f / (KG - 1))) * LOG2E;
    int chunk = (m + JS - 1) / JS;
    int j0 = blockIdx.z * chunk;
    int j1 = min(j0 + chunk, m);
    const float* __restrict__ A = g_A[sl];
    const float* __restrict__ U = g_U[sl];
    float a0 = 0.f, a1 = 0.f, a2 = 0.f, a3 = 0.f;
    int j = j0;
    for (; j + 4 <= j1; j += 4) {
        a0 = fmaf(U[j],     ex2(A[j]     * tl), a0);
        a1 = fmaf(U[j + 1], ex2(A[j + 1] * tl), a1);
        a2 = fmaf(U[j + 2], ex2(A[j + 2] * tl), a2);
        a3 = fmaf(U[j + 3], ex2(A[j + 3] * tl), a3);
    }
    for (; j < j1; j++) a0 = fmaf(U[j], ex2(A[j] * tl), a0);
    g_Gp[sl][blockIdx.z][k] = (a0 + a1) + (a2 + a3);
}

// ---------------- reduce G, evaluate Patt for every position ----------------
__global__ void patt_kernel() {
    int sl = blockIdx.x;
    int t = threadIdx.x;                  // 512
    float qmax = g_qmax[sl];
    __shared__ float shG[KG];
    float g = 0.f;
    #pragma unroll
    for (int j = 0; j < JS; j++) g += g_Gp[sl][j][t];
    shG[t] = g;
    __syncthreads();

    float inv = (qmax > 0.f) ? (float)(KG - 1) / qmax : 0.f;
    float s0n = g_s0n[sl];
    int base = sl * 4096 + blockIdx.y * 1024;
    #pragma unroll
    for (int k = 0; k < 2; k++) {
        int gi = base + k * 512 + t;
        float q = g_q[gi];
        float u = q * inv;
        int k0 = min((int)u, KG - 2);
        float fr = u - (float)k0;
        g_patt[gi] = fmaf(shG[k0 + 1] - shG[k0], fr, shG[k0]) + s0n;
    }
}

// ---------------- depth attention (D=3) + epilogue ----------------
__global__ void final_kernel(const float* __restrict__ x, const float* __restrict__ gama,
                             float* __restrict__ out) {
    int idx = blockIdx.x * blockDim.x + threadIdx.x;   // c*4096 + p
    if (idx >= 16384) return;
    int c = idx >> 12;
    int p = idx & 4095;
    int base = c * 12288 + p;

    float qv[3], vv[3];
    #pragma unroll
    for (int d = 0; d < 3; d++) { qv[d] = g_q[base + d * 4096]; vv[d] = g_v[base + d * 4096]; }
    float qm = fmaxf(qv[0], fmaxf(qv[1], qv[2]));

    float datt0 = 0.f, datt1 = 0.f, datt2 = 0.f;
    #pragma unroll
    for (int i = 0; i < 3; i++) {
        float e0 = ex2(qv[i] * (qv[0] - qm) * LOG2E);
        float e1 = ex2(qv[i] * (qv[1] - qm) * LOG2E);
        float e2 = ex2(qv[i] * (qv[2] - qm) * LOG2E);
        float rz = vv[i] / (e0 + e1 + e2);
        datt0 = fmaf(rz, e0, datt0);
        datt1 = fmaf(rz, e1, datt1);
        datt2 = fmaf(rz, e2, datt2);
    }
    float datt[3] = {datt0, datt1, datt2};
    float g = gama[0];
    #pragma unroll
    for (int d = 0; d < 3; d++) {
        int gi = base + d * 4096;
        out[gi] = fmaf(g, g_patt[gi] + datt[d], x[gi]);
    }
}

// ---------------- launch ----------------
extern "C" void kernel_launch(void* const* d_in, const int* in_sizes, int n_in,
                              void* d_out, int out_size) {
    const float* x    = (const float*)d_in[0];
    const float* W3   = (const float*)d_in[1];
    const float* b3   = (const float*)d_in[2];
    const float* g3   = (const float*)d_in[3];
    const float* be3  = (const float*)d_in[4];
    const float* W1   = (const float*)d_in[5];
    const float* b1   = (const float*)d_in[6];
    const float* g1   = (const float*)d_in[7];
    const float* be1  = (const float*)d_in[8];
    const float* gama = (const float*)d_in[9];
    float* out = (float*)d_out;

    conv_kernel<<<192, 256>>>(x, W3, b3, W1, b1);
    stats_kernel<<<8, 256>>>(g3, be3, g1, be1);
    prep_kernel<<<12, 512>>>();
    gridF_kernel<<<dim3(12, KG / 128, JS), 128>>>();
    wpass_kernel<<<dim3(12, 4), 512>>>();
    gridG_kernel<<<dim3(12, KG / 128, JS), 128>>>();
    patt_kernel<<<dim3(12, 4), 512>>>();
    final_kernel<<<64, 256>>>(x, gama, out);
}

// round 3
// speedup vs baseline: 1.7994x; 1.3989x over previous
#include <cuda_runtime.h>

#define LOG2E 1.4426950408889634f
#define KG 128           // interpolation grid size (one per thread in grid kernels)
#define JSF 32           // j-splits for grid kernels
#define CH 128           // max j-chunk = ceil(4096/JSF)

// ---------------- scratch ----------------
__device__ float g_conv3[49152];
__device__ float g_conv1[49152];
__device__ float g_v[49152];
__device__ float g_q[49152];
__device__ float g_scale[16];     // [0:4) scale3 [4:8) shift3 [8:12) scale1 [12:16) shift1
__device__ int   g_m[12];
__device__ float g_qmax[12];
__device__ float g_s0n[12];
__device__ float g_A[12][4096];   // compacted nonzero q
__device__ float g_Vnz[12][4096]; // v at those positions
__device__ float g_U[12][4096];   // u_i coefficients for G
__device__ float g_Fp[12][JSF][KG];
__device__ float g_Gp[12][JSF][KG];

__device__ __forceinline__ float ex2(float x) {
    float y; asm("ex2.approx.ftz.f32 %0, %1;" : "=f"(y) : "f"(x)); return y;
}

// ---------------- conv3x3x3 (pad 1) + conv1x1x1 fused ----------------
__global__ void conv_kernel(const float* __restrict__ x, const float* __restrict__ W3,
                            const float* __restrict__ b3, const float* __restrict__ W1,
                            const float* __restrict__ b1) {
    int idx = blockIdx.x * blockDim.x + threadIdx.x;
    if (idx >= 49152) return;
    int c = idx / 12288;
    int r = idx - c * 12288;
    int d = r >> 12;
    int p = r & 4095;
    int h = p >> 6;
    int w = p & 63;

    float acc = b3[c];
    #pragma unroll
    for (int ci = 0; ci < 4; ci++) {
        const float* wp = W3 + (c * 4 + ci) * 27;
        const float* xp = x + ci * 12288;
        #pragma unroll
        for (int kd = 0; kd < 3; kd++) {
            int zd = d + kd - 1;
            if ((unsigned)zd >= 3u) continue;
            #pragma unroll
            for (int kh = 0; kh < 3; kh++) {
                int zh = h + kh - 1;
                if ((unsigned)zh >= 64u) continue;
                #pragma unroll
                for (int kw = 0; kw < 3; kw++) {
                    int zw = w + kw - 1;
                    if ((unsigned)zw >= 64u) continue;
                    acc += wp[kd * 9 + kh * 3 + kw] * xp[zd * 4096 + zh * 64 + zw];
                }
            }
        }
    }
    g_conv3[idx] = acc;

    float acc1 = b1[c];
    #pragma unroll
    for (int ci = 0; ci < 4; ci++)
        acc1 += W1[c * 4 + ci] * x[ci * 12288 + d * 4096 + p];
    g_conv1[idx] = acc1;
}

// ---------------- BatchNorm batch stats ----------------
__global__ void stats_kernel(const float* __restrict__ g3, const float* __restrict__ be3,
                             const float* __restrict__ g1, const float* __restrict__ be1) {
    int ch = blockIdx.x;  // 0..3 conv3, 4..7 conv1
    const float* src = (ch < 4) ? g_conv3 : g_conv1;
    int c = ch & 3;
    const float4* pp = (const float4*)(src + c * 12288);
    float s = 0.f, sq = 0.f;
    for (int i = threadIdx.x; i < 3072; i += 256) {
        float4 v = pp[i];
        s += (v.x + v.y) + (v.z + v.w);
        sq += (v.x * v.x + v.y * v.y) + (v.z * v.z + v.w * v.w);
    }
    for (int o = 16; o > 0; o >>= 1) {
        s  += __shfl_xor_sync(0xffffffffu, s, o);
        sq += __shfl_xor_sync(0xffffffffu, sq, o);
    }
    __shared__ float sh1[8], sh2[8];
    int wid = threadIdx.x >> 5, lane = threadIdx.x & 31;
    if (lane == 0) { sh1[wid] = s; sh2[wid] = sq; }
    __syncthreads();
    if (threadIdx.x == 0) {
        float S = 0.f, SQ = 0.f;
        #pragma unroll
        for (int i = 0; i < 8; i++) { S += sh1[i]; SQ += sh2[i]; }
        float mean = S * (1.f / 12288.f);
        float var  = SQ * (1.f / 12288.f) - mean * mean;
        float rstd = rsqrtf(var + 1e-5f);
        float gamma = (ch < 4) ? g3[c] : g1[c];
        float beta  = (ch < 4) ? be3[c] : be1[c];
        float sc = gamma * rstd;
        int o = (ch < 4) ? 0 : 8;
        g_scale[o + c]     = sc;
        g_scale[o + 4 + c] = beta - mean * sc;
    }
}

// ---------------- bn+relu, per-slice qmax / compaction / zero-v sum ----------------
__global__ void prep_kernel() {
    int sl = blockIdx.x;
    int base = sl * 4096;
    int t = threadIdx.x;                 // 512
    int c = sl / 3;
    int lane = t & 31, wid = t >> 5;
    __shared__ float shf[16];
    __shared__ float shs[16];
    __shared__ int   shw[16];

    float sc3 = g_scale[c],     sh3 = g_scale[4 + c];
    float sc1 = g_scale[8 + c], sh1 = g_scale[12 + c];

    float qv[8], vv[8];
    int b0 = base + t * 8;
    #pragma unroll
    for (int k = 0; k < 8; k++) {
        int j = b0 + k;
        qv[k] = fmaxf(fmaf(g_conv1[j], sc1, sh1), 0.f);
        vv[k] = fmaxf(fmaf(g_conv3[j], sc3, sh3), 0.f);
        g_q[j] = qv[k];
        g_v[j] = vv[k];
    }

    float mx = 0.f, s0 = 0.f;
    int cnt = 0;
    #pragma unroll
    for (int k = 0; k < 8; k++) {
        mx = fmaxf(mx, qv[k]);
        if (qv[k] > 0.f) cnt++; else s0 += vv[k];
    }
    float m2 = mx, z2 = s0;
    for (int o = 16; o > 0; o >>= 1) {
        m2 = fmaxf(m2, __shfl_xor_sync(0xffffffffu, m2, o));
        z2 += __shfl_xor_sync(0xffffffffu, z2, o);
    }
    int inc = cnt;
    #pragma unroll
    for (int o = 1; o < 32; o <<= 1) {
        int n = __shfl_up_sync(0xffffffffu, inc, o);
        if (lane >= o) inc += n;
    }
    if (lane == 31) shw[wid] = inc;
    if (lane == 0) { shf[wid] = m2; shs[wid] = z2; }
    __syncthreads();
    if (wid == 0) {
        int sv = (lane < 16) ? shw[lane] : 0;
        #pragma unroll
        for (int o = 1; o < 16; o <<= 1) {
            int n = __shfl_up_sync(0xffffffffu, sv, o);
            if (lane >= o) sv += n;
        }
        if (lane < 16) shw[lane] = sv;
        float fm = (lane < 16) ? shf[lane] : 0.f;
        float fz = (lane < 16) ? shs[lane] : 0.f;
        for (int o = 8; o > 0; o >>= 1) {
            fm = fmaxf(fm, __shfl_xor_sync(0xffffffffu, fm, o));
            fz += __shfl_xor_sync(0xffffffffu, fz, o);
        }
        if (lane == 0) { shf[0] = fm; shs[0] = fz; }
    }
    __syncthreads();

    int off = (wid ? shw[wid - 1] : 0) + inc - cnt;
    #pragma unroll
    for (int k = 0; k < 8; k++) {
        if (qv[k] > 0.f) {
            g_A[sl][off]   = qv[k];
            g_Vnz[sl][off] = vv[k];
            off++;
        }
    }
    if (t == 0) {
        g_m[sl]    = shw[15];
        g_qmax[sl] = shf[0];
        g_s0n[sl]  = shs[0] * (1.f / 4096.f);
    }
}

// ---------------- F(t_k) partials: sum_j exp(t_k*(q_j - qmax)), smem-staged ----------------
__global__ void gridF_kernel() {
    int sl = blockIdx.x;
    int m = g_m[sl];
    __shared__ __align__(16) float shA[CH];
    int chunk = (m + JSF - 1) / JSF;
    int j0 = blockIdx.y * chunk;
    int n = min(chunk, m - j0);
    if (n < 0) n = 0;
    for (int i = threadIdx.x; i < n; i += 128) shA[i] = g_A[sl][j0 + i];
    __syncthreads();

    float qmax = g_qmax[sl];
    float tl = (float)threadIdx.x * (qmax * (1.f / (KG - 1))) * LOG2E;
    float cn = -qmax * tl;
    float a0 = 0.f, a1 = 0.f, a2 = 0.f, a3 = 0.f;
    int n4 = n >> 2;
    const float4* A4 = (const float4*)shA;
    for (int i = 0; i < n4; i++) {
        float4 a = A4[i];
        a0 += ex2(fmaf(a.x, tl, cn));
        a1 += ex2(fmaf(a.y, tl, cn));
        a2 += ex2(fmaf(a.z, tl, cn));
        a3 += ex2(fmaf(a.w, tl, cn));
    }
    for (int i = n4 * 4; i < n; i++) a0 += ex2(fmaf(shA[i], tl, cn));
    g_Fp[sl][blockIdx.y][threadIdx.x] = (a0 + a1) + (a2 + a3);
}

// ---------------- reduce F, compute u_i per nonzero row ----------------
__global__ void wpass_kernel() {
    int sl = blockIdx.x;
    int m = g_m[sl];
    int t = threadIdx.x;                  // 256
    float qmax = g_qmax[sl];
    __shared__ float shF[KG];
    if (t < KG) {
        float f = 0.f;
        #pragma unroll
        for (int j = 0; j < JSF; j++) f += g_Fp[sl][j][t];
        float tk = (float)t * (qmax * (1.f / (KG - 1)));
        f += (float)(4096 - m) * ex2(-tk * qmax * LOG2E);
        shF[t] = f;
    }
    __syncthreads();

    float inv = (qmax > 0.f) ? (float)(KG - 1) / qmax : 0.f;
    float bz = -qmax * LOG2E;
    int rpb = (m + 1) / 2;
    int r0 = blockIdx.y * rpb;
    int r1 = min(r0 + rpb, m);
    for (int r = r0 + t; r < r1; r += 256) {
        float q = g_A[sl][r];
        float u = q * inv;
        int k0 = min((int)u, KG - 2);
        float fr = u - (float)k0;
        float F = fmaf(shF[k0 + 1] - shF[k0], fr, shF[k0]);
        g_U[sl][r] = (g_Vnz[sl][r] / F) * ex2(q * bz);
    }
}

// ---------------- G(t_k) partials: sum_i u_i exp(t_k*q_i), smem-staged ----------------
__global__ void gridG_kernel() {
    int sl = blockIdx.x;
    int m = g_m[sl];
    __shared__ __align__(16) float shA[CH];
    __shared__ __align__(16) float shU[CH];
    int chunk = (m + JSF - 1) / JSF;
    int j0 = blockIdx.y * chunk;
    int n = min(chunk, m - j0);
    if (n < 0) n = 0;
    for (int i = threadIdx.x; i < n; i += 128) {
        shA[i] = g_A[sl][j0 + i];
        shU[i] = g_U[sl][j0 + i];
    }
    __syncthreads();

    float qmax = g_qmax[sl];
    float tl = (float)threadIdx.x * (qmax * (1.f / (KG - 1))) * LOG2E;
    float a0 = 0.f, a1 = 0.f, a2 = 0.f, a3 = 0.f;
    int n4 = n >> 2;
    const float4* A4 = (const float4*)shA;
    const float4* U4 = (const float4*)shU;
    for (int i = 0; i < n4; i++) {
        float4 a = A4[i];
        float4 u = U4[i];
        a0 = fmaf(u.x, ex2(a.x * tl), a0);
        a1 = fmaf(u.y, ex2(a.y * tl), a1);
        a2 = fmaf(u.z, ex2(a.z * tl), a2);
        a3 = fmaf(u.w, ex2(a.w * tl), a3);
    }
    for (int i = n4 * 4; i < n; i++) a0 = fmaf(shU[i], ex2(shA[i] * tl), a0);
    g_Gp[sl][blockIdx.y][threadIdx.x] = (a0 + a1) + (a2 + a3);
}

// ---------------- reduce G + Patt interp + depth attention + epilogue ----------------
__global__ void final_kernel(const float* __restrict__ x, const float* __restrict__ gama,
                             float* __restrict__ out) {
    int tid = threadIdx.x;                       // 256
    int c = blockIdx.x >> 4;                     // 16 blocks per channel
    __shared__ float shG[3][KG];

    for (int i = tid; i < 3 * KG; i += 256) {
        int d = i >> 7, k = i & (KG - 1);
        int sl = c * 3 + d;
        float s = 0.f;
        #pragma unroll
        for (int j = 0; j < JSF; j++) s += g_Gp[sl][j][k];
        shG[d][k] = s;
    }
    __syncthreads();

    float inv[3], s0n[3];
    #pragma unroll
    for (int d = 0; d < 3; d++) {
        float qm = g_qmax[c * 3 + d];
        inv[d] = (qm > 0.f) ? (float)(KG - 1) / qm : 0.f;
        s0n[d] = g_s0n[c * 3 + d];
    }

    int p = (blockIdx.x & 15) * 256 + tid;
    int base = c * 12288 + p;

    float qv[3], vv[3], patt[3];
    #pragma unroll
    for (int d = 0; d < 3; d++) {
        qv[d] = g_q[base + d * 4096];
        vv[d] = g_v[base + d * 4096];
        float u = qv[d] * inv[d];
        int k0 = min((int)u, KG - 2);
        float fr = u - (float)k0;
        patt[d] = fmaf(shG[d][k0 + 1] - shG[d][k0], fr, shG[d][k0]) + s0n[d];
    }

    float qm = fmaxf(qv[0], fmaxf(qv[1], qv[2]));
    float datt0 = 0.f, datt1 = 0.f, datt2 = 0.f;
    #pragma unroll
    for (int i = 0; i < 3; i++) {
        float e0 = ex2(qv[i] * (qv[0] - qm) * LOG2E);
        float e1 = ex2(qv[i] * (qv[1] - qm) * LOG2E);
        float e2 = ex2(qv[i] * (qv[2] - qm) * LOG2E);
        float rz = vv[i] / (e0 + e1 + e2);
        datt0 = fmaf(rz, e0, datt0);
        datt1 = fmaf(rz, e1, datt1);
        datt2 = fmaf(rz, e2, datt2);
    }
    float datt[3] = {datt0, datt1, datt2};
    float g = gama[0];
    #pragma unroll
    for (int d = 0; d < 3; d++) {
        int gi = base + d * 4096;
        out[gi] = fmaf(g, patt[d] + datt[d], x[gi]);
    }
}

// ---------------- launch ----------------
extern "C" void kernel_launch(void* const* d_in, const int* in_sizes, int n_in,
                              void* d_out, int out_size) {
    const float* x    = (const float*)d_in[0];
    const float* W3   = (const float*)d_in[1];
    const float* b3   = (const float*)d_in[2];
    const float* g3   = (const float*)d_in[3];
    const float* be3  = (const float*)d_in[4];
    const float* W1   = (const float*)d_in[5];
    const float* b1   = (const float*)d_in[6];
    const float* g1   = (const float*)d_in[7];
    const float* be1  = (const float*)d_in[8];
    const float* gama = (const float*)d_in[9];
    float* out = (float*)d_out;

    conv_kernel<<<192, 256>>>(x, W3, b3, W1, b1);
    stats_kernel<<<8, 256>>>(g3, be3, g1, be1);
    prep_kernel<<<12, 512>>>();
    gridF_kernel<<<dim3(12, JSF), 128>>>();
    wpass_kernel<<<dim3(12, 2), 256>>>();
    gridG_kernel<<<dim3(12, JSF), 128>>>();
    final_kernel<<<64, 256>>>(x, gama, out);
}

// round 4
// speedup vs baseline: 2.3861x; 1.3261x over previous
#include <cuda_runtime.h>

#define LOG2E 1.4426950408889634f
#define KG 64            // interpolation grid size
#define JSG 32           // j-splits for grid kernels
#define CH 128           // max j-chunk = ceil(4096/JSG)

// ---------------- scratch ----------------
__device__ float g_conv3[49152];
__device__ float g_conv1[49152];
__device__ float g_v[49152];
__device__ float g_q[49152];
__device__ float g_part[96 * 16];  // per conv-block: [0:4) s3 [4:8) sq3 [8:12) s1 [12:16) sq1
__device__ int   g_m[12];
__device__ float g_qmax[12];
__device__ float g_s0n[12];
__device__ float g_A[12][4096];    // compacted nonzero q
__device__ float g_Vnz[12][4096];  // v at those positions
__device__ float g_Fp[12][JSG][KG];
__device__ float g_Gp[12][JSG][KG];

__device__ __forceinline__ float ex2(float x) {
    float y; asm("ex2.approx.ftz.f32 %0, %1;" : "=f"(y) : "f"(x)); return y;
}

// ---------------- conv3 + conv1 (all 4 c_out per thread) + stats partials ----------------
__global__ void conv_kernel(const float* __restrict__ x, const float* __restrict__ W3,
                            const float* __restrict__ b3, const float* __restrict__ W1,
                            const float* __restrict__ b1) {
    __shared__ float shW3[432];   // [co][ci][27]
    __shared__ float shW1[16];
    __shared__ float shB3[4], shB1[4];
    __shared__ float smp[4][16];

    int t = threadIdx.x;          // 128
    for (int i = t; i < 432; i += 128) shW3[i] = W3[i];
    if (t < 16) shW1[t] = W1[t];
    if (t < 4)  { shB3[t] = b3[t]; shB1[t] = b1[t]; }
    __syncthreads();

    int idx = blockIdx.x * 128 + t;      // (d,p): 12288 total
    int d = idx >> 12;
    int p = idx & 4095;
    int h = p >> 6;
    int w = p & 63;

    float acc[4]  = {shB3[0], shB3[1], shB3[2], shB3[3]};
    float acc1[4] = {shB1[0], shB1[1], shB1[2], shB1[3]};

    #pragma unroll
    for (int ci = 0; ci < 4; ci++) {
        const float* xp = x + ci * 12288;
        #pragma unroll
        for (int kd = 0; kd < 3; kd++) {
            int zd = d + kd - 1;
            if ((unsigned)zd >= 3u) continue;
            #pragma unroll
            for (int kh = 0; kh < 3; kh++) {
                int zh = h + kh - 1;
                if ((unsigned)zh >= 64u) continue;
                #pragma unroll
                for (int kw = 0; kw < 3; kw++) {
                    int zw = w + kw - 1;
                    if ((unsigned)zw >= 64u) continue;
                    float xv = xp[zd * 4096 + zh * 64 + zw];
                    int ki = kd * 9 + kh * 3 + kw;
                    #pragma unroll
                    for (int co = 0; co < 4; co++)
                        acc[co] = fmaf(shW3[(co * 4 + ci) * 27 + ki], xv, acc[co]);
                }
            }
        }
        float xc = xp[d * 4096 + p];
        #pragma unroll
        for (int co = 0; co < 4; co++)
            acc1[co] = fmaf(shW1[co * 4 + ci], xc, acc1[co]);
    }

    #pragma unroll
    for (int co = 0; co < 4; co++) {
        g_conv3[co * 12288 + idx] = acc[co];
        g_conv1[co * 12288 + idx] = acc1[co];
    }

    // per-block stats partials: 16 reductions over 128 threads
    float red[16];
    #pragma unroll
    for (int co = 0; co < 4; co++) {
        red[co]      = acc[co];
        red[4 + co]  = acc[co] * acc[co];
        red[8 + co]  = acc1[co];
        red[12 + co] = acc1[co] * acc1[co];
    }
    #pragma unroll
    for (int j = 0; j < 16; j++)
        for (int o = 16; o > 0; o >>= 1)
            red[j] += __shfl_xor_sync(0xffffffffu, red[j], o);
    int lane = t & 31, wid = t >> 5;
    if (lane == 0) {
        #pragma unroll
        for (int j = 0; j < 16; j++) smp[wid][j] = red[j];
    }
    __syncthreads();
    if (t < 16)
        g_part[blockIdx.x * 16 + t] = (smp[0][t] + smp[1][t]) + (smp[2][t] + smp[3][t]);
}

// ---------------- stats finalize + bn+relu + qmax / compaction / zero-v sum ----------------
__global__ void prep_kernel(const float* __restrict__ g3, const float* __restrict__ be3,
                            const float* __restrict__ g1, const float* __restrict__ be1) {
    int sl = blockIdx.x;
    int base = sl * 4096;
    int t = threadIdx.x;                 // 512
    int c = sl / 3;
    int lane = t & 31, wid = t >> 5;
    __shared__ float shsc[4];            // sc3, sh3, sc1, sh1
    __shared__ float shf[16];
    __shared__ float shs[16];
    __shared__ int   shw[16];

    // warp 0: reduce stats partials for channel c
    if (wid == 0) {
        float s3 = 0.f, q3 = 0.f, s1 = 0.f, q1 = 0.f;
        for (int b = lane; b < 96; b += 32) {
            const float* P = g_part + b * 16;
            s3 += P[c]; q3 += P[4 + c]; s1 += P[8 + c]; q1 += P[12 + c];
        }
        for (int o = 16; o > 0; o >>= 1) {
            s3 += __shfl_xor_sync(0xffffffffu, s3, o);
            q3 += __shfl_xor_sync(0xffffffffu, q3, o);
            s1 += __shfl_xor_sync(0xffffffffu, s1, o);
            q1 += __shfl_xor_sync(0xffffffffu, q1, o);
        }
        if (lane == 0) {
            float mean3 = s3 * (1.f / 12288.f);
            float var3  = q3 * (1.f / 12288.f) - mean3 * mean3;
            float sc3 = g3[c] * rsqrtf(var3 + 1e-5f);
            float mean1 = s1 * (1.f / 12288.f);
            float var1  = q1 * (1.f / 12288.f) - mean1 * mean1;
            float sc1 = g1[c] * rsqrtf(var1 + 1e-5f);
            shsc[0] = sc3; shsc[1] = be3[c] - mean3 * sc3;
            shsc[2] = sc1; shsc[3] = be1[c] - mean1 * sc1;
        }
    }
    __syncthreads();

    float sc3 = shsc[0], sh3 = shsc[1], sc1 = shsc[2], sh1v = shsc[3];

    float qv[8], vv[8];
    int b0 = base + t * 8;
    #pragma unroll
    for (int k = 0; k < 8; k++) {
        int j = b0 + k;
        qv[k] = fmaxf(fmaf(g_conv1[j], sc1, sh1v), 0.f);
        vv[k] = fmaxf(fmaf(g_conv3[j], sc3, sh3),  0.f);
        g_q[j] = qv[k];
        g_v[j] = vv[k];
    }

    float mx = 0.f, s0 = 0.f;
    int cnt = 0;
    #pragma unroll
    for (int k = 0; k < 8; k++) {
        mx = fmaxf(mx, qv[k]);
        if (qv[k] > 0.f) cnt++; else s0 += vv[k];
    }
    float m2 = mx, z2 = s0;
    for (int o = 16; o > 0; o >>= 1) {
        m2 = fmaxf(m2, __shfl_xor_sync(0xffffffffu, m2, o));
        z2 += __shfl_xor_sync(0xffffffffu, z2, o);
    }
    int inc = cnt;
    #pragma unroll
    for (int o = 1; o < 32; o <<= 1) {
        int n = __shfl_up_sync(0xffffffffu, inc, o);
        if (lane >= o) inc += n;
    }
    if (lane == 31) shw[wid] = inc;
    if (lane == 0) { shf[wid] = m2; shs[wid] = z2; }
    __syncthreads();
    if (wid == 0) {
        int sv = (lane < 16) ? shw[lane] : 0;
        #pragma unroll
        for (int o = 1; o < 16; o <<= 1) {
            int n = __shfl_up_sync(0xffffffffu, sv, o);
            if (lane >= o) sv += n;
        }
        if (lane < 16) shw[lane] = sv;
        float fm = (lane < 16) ? shf[lane] : 0.f;
        float fz = (lane < 16) ? shs[lane] : 0.f;
        for (int o = 8; o > 0; o >>= 1) {
            fm = fmaxf(fm, __shfl_xor_sync(0xffffffffu, fm, o));
            fz += __shfl_xor_sync(0xffffffffu, fz, o);
        }
        if (lane == 0) { shf[0] = fm; shs[0] = fz; }
    }
    __syncthreads();

    int off = (wid ? shw[wid - 1] : 0) + inc - cnt;
    #pragma unroll
    for (int k = 0; k < 8; k++) {
        if (qv[k] > 0.f) {
            g_A[sl][off]   = qv[k];
            g_Vnz[sl][off] = vv[k];
            off++;
        }
    }
    if (t == 0) {
        g_m[sl]    = shw[15];
        g_qmax[sl] = shf[0];
        g_s0n[sl]  = shs[0] * (1.f / 4096.f);
    }
}

// ---------------- F(t_k) partials: 64 grid points x 4 j-lanes per block ----------------
__global__ void gridF_kernel() {
    int sl = blockIdx.x;
    int m = g_m[sl];
    int t = threadIdx.x;                 // 256
    __shared__ float shA[CH];
    __shared__ float shP[4][KG];
    int chunk = (m + JSG - 1) >> 5;
    int j0 = blockIdx.y * chunk;
    int n = m - j0; if (n > chunk) n = chunk; if (n < 0) n = 0;
    for (int i = t; i < n; i += 256) shA[i] = g_A[sl][j0 + i];
    __syncthreads();

    int k = t & 63, lane = t >> 6;
    float qmax = g_qmax[sl];
    float tl = (float)k * (qmax * (1.f / (KG - 1))) * LOG2E;
    float cn = -qmax * tl;
    float a0 = 0.f, a1 = 0.f;
    int i = lane;
    for (; i + 4 < n; i += 8) {
        a0 += ex2(fmaf(shA[i],     tl, cn));
        a1 += ex2(fmaf(shA[i + 4], tl, cn));
    }
    for (; i < n; i += 4) a0 += ex2(fmaf(shA[i], tl, cn));
    shP[lane][k] = a0 + a1;
    __syncthreads();
    if (t < KG)
        g_Fp[sl][blockIdx.y][t] = (shP[0][t] + shP[1][t]) + (shP[2][t] + shP[3][t]);
}

// ---------------- reduce F + compute chunk U + G(t_k) partials ----------------
__global__ void gridG_kernel() {
    int sl = blockIdx.x;
    int m = g_m[sl];
    int t = threadIdx.x;                 // 256
    float qmax = g_qmax[sl];
    __shared__ float shF[KG];
    __shared__ float shA[CH], shU[CH];
    __shared__ float shP[4][KG];

    if (t < KG) {
        float f = 0.f;
        #pragma unroll
        for (int j = 0; j < JSG; j++) f += g_Fp[sl][j][t];
        float tk = (float)t * (qmax * (1.f / (KG - 1)));
        f += (float)(4096 - m) * ex2(-tk * qmax * LOG2E);
        shF[t] = f;
    }
    int chunk = (m + JSG - 1) >> 5;
    int j0 = blockIdx.y * chunk;
    int n = m - j0; if (n > chunk) n = chunk; if (n < 0) n = 0;
    for (int i = t; i < n; i += 256) shA[i] = g_A[sl][j0 + i];
    __syncthreads();

    float inv = (qmax > 0.f) ? (float)(KG - 1) / qmax : 0.f;
    float bz = -qmax * LOG2E;
    for (int i = t; i < n; i += 256) {
        float q = shA[i];
        float u = q * inv;
        int k0 = min((int)u, KG - 2);
        float fr = u - (float)k0;
        float F = fmaf(shF[k0 + 1] - shF[k0], fr, shF[k0]);
        shU[i] = (g_Vnz[sl][j0 + i] / F) * ex2(q * bz);
    }
    __syncthreads();

    int k = t & 63, lane = t >> 6;
    float tl = (float)k * (qmax * (1.f / (KG - 1))) * LOG2E;
    float a0 = 0.f, a1 = 0.f;
    int i = lane;
    for (; i + 4 < n; i += 8) {
        a0 = fmaf(shU[i],     ex2(shA[i]     * tl), a0);
        a1 = fmaf(shU[i + 4], ex2(shA[i + 4] * tl), a1);
    }
    for (; i < n; i += 4) a0 = fmaf(shU[i], ex2(shA[i] * tl), a0);
    shP[lane][k] = a0 + a1;
    __syncthreads();
    if (t < KG)
        g_Gp[sl][blockIdx.y][t] = (shP[0][t] + shP[1][t]) + (shP[2][t] + shP[3][t]);
}

// ---------------- reduce G + Patt interp + depth attention + epilogue ----------------
__global__ void final_kernel(const float* __restrict__ x, const float* __restrict__ gama,
                             float* __restrict__ out) {
    int tid = threadIdx.x;                       // 256
    int c = blockIdx.x >> 4;                     // 16 blocks per channel
    __shared__ float shG[3][KG];

    if (tid < 3 * KG) {
        int d = tid >> 6, k = tid & (KG - 1);
        int sl = c * 3 + d;
        float s = 0.f;
        #pragma unroll
        for (int j = 0; j < JSG; j++) s += g_Gp[sl][j][k];
        shG[d][k] = s;
    }
    __syncthreads();

    float inv[3], s0n[3];
    #pragma unroll
    for (int d = 0; d < 3; d++) {
        float qm = g_qmax[c * 3 + d];
        inv[d] = (qm > 0.f) ? (float)(KG - 1) / qm : 0.f;
        s0n[d] = g_s0n[c * 3 + d];
    }

    int p = (blockIdx.x & 15) * 256 + tid;
    int base = c * 12288 + p;

    float qv[3], vv[3], patt[3];
    #pragma unroll
    for (int d = 0; d < 3; d++) {
        qv[d] = g_q[base + d * 4096];
        vv[d] = g_v[base + d * 4096];
        float u = qv[d] * inv[d];
        int k0 = min((int)u, KG - 2);
        float fr = u - (float)k0;
        patt[d] = fmaf(shG[d][k0 + 1] - shG[d][k0], fr, shG[d][k0]) + s0n[d];
    }

    float qm = fmaxf(qv[0], fmaxf(qv[1], qv[2]));
    float datt0 = 0.f, datt1 = 0.f, datt2 = 0.f;
    #pragma unroll
    for (int i = 0; i < 3; i++) {
        float e0 = ex2(qv[i] * (qv[0] - qm) * LOG2E);
        float e1 = ex2(qv[i] * (qv[1] - qm) * LOG2E);
        float e2 = ex2(qv[i] * (qv[2] - qm) * LOG2E);
        float rz = vv[i] / (e0 + e1 + e2);
        datt0 = fmaf(rz, e0, datt0);
        datt1 = fmaf(rz, e1, datt1);
        datt2 = fmaf(rz, e2, datt2);
    }
    float datt[3] = {datt0, datt1, datt2};
    float g = gama[0];
    #pragma unroll
    for (int d = 0; d < 3; d++) {
        int gi = base + d * 4096;
        out[gi] = fmaf(g, patt[d] + datt[d], x[gi]);
    }
}

// ---------------- launch ----------------
extern "C" void kernel_launch(void* const* d_in, const int* in_sizes, int n_in,
                              void* d_out, int out_size) {
    const float* x    = (const float*)d_in[0];
    const float* W3   = (const float*)d_in[1];
    const float* b3   = (const float*)d_in[2];
    const float* g3   = (const float*)d_in[3];
    const float* be3  = (const float*)d_in[4];
    const float* W1   = (const float*)d_in[5];
    const float* b1   = (const float*)d_in[6];
    const float* g1   = (const float*)d_in[7];
    const float* be1  = (const float*)d_in[8];
    const float* gama = (const float*)d_in[9];
    float* out = (float*)d_out;

    conv_kernel<<<96, 128>>>(x, W3, b3, W1, b1);
    prep_kernel<<<12, 512>>>(g3, be3, g1, be1);
    gridF_kernel<<<dim3(12, JSG), 256>>>();
    gridG_kernel<<<dim3(12, JSG), 256>>>();
    final_kernel<<<64, 256>>>(x, gama, out);
}